// round 6
// baseline (speedup 1.0000x reference)
#include <cuda_runtime.h>
#include <cuda_bf16.h>

#define BATCH    65536
#define N_WIRES  4
#define N_LAYERS 3
#define BN_EPS   1e-5f
#define SIM_BLOCKS (BATCH / 16)      // 4096 blocks, 16 samples each
#define BN_BLOCKS  128               // 512 samples per bn block

// Scratch (no cudaMalloc allowed)
__device__ float g_part[SIM_BLOCKS * 8];   // per-block BN partials: 4 sums + 4 sumsq
__device__ float g_pre[BATCH * 4];         // pre-BN linear outputs

// ---------------------------------------------------------------------------
// Kernel 1: encode (chunk means) + 4-qubit statevector sim (16 lanes = 16
// amplitudes, 2 samples per warp) + Linear(4,4) + per-block BN partials.
// Gate matrices M = RX@RZ are computed locally per block (no prep kernel).
// ---------------------------------------------------------------------------
__global__ void __launch_bounds__(256) sim_kernel(const float* __restrict__ x,
                                                  const float* __restrict__ params,
                                                  const float* __restrict__ Wg,
                                                  const float* __restrict__ bg) {
    __shared__ float sM[96];     // [l][w][row][col][ri]
    __shared__ float sAcc[8];
    int tid = threadIdx.x;
    if (tid < 8) sAcc[tid] = 0.0f;
    if (tid < 12) {   // tid = l*4 + w : build fused M = RX(t1) @ RZ(t0)
        float t0 = params[tid * 3 + 0];
        float t1 = params[tid * 3 + 1];
        float c0, s0, c1, s1;
        sincosf(0.5f * t0, &s0, &c0);
        sincosf(0.5f * t1, &s1, &c1);
        float2* Mo = (float2*)sM;
        Mo[tid * 4 + 0] = make_float2( c1 * c0, -c1 * s0);
        Mo[tid * 4 + 1] = make_float2( s1 * s0, -s1 * c0);
        Mo[tid * 4 + 2] = make_float2(-s1 * s0, -s1 * c0);
        Mo[tid * 4 + 3] = make_float2( c1 * c0,  c1 * s0);
    }
    __syncthreads();

    int lane = tid & 31;
    int warp = tid >> 5;
    int sA = (blockIdx.x * 8 + warp) * 2;   // warp handles samples sA, sA+1

    // ---- encoding: mean of 4 chunks of 196 floats (49 float4 each) ----
    // lanes split into 4 groups of 8; group g sums chunk g (for both samples).
    const float4* x4 = (const float4*)x;
    int g  = lane >> 3;
    int j8 = lane & 7;
    const float4* pA = x4 + (size_t)sA * 196 + g * 49 + j8;
    float sum_a = 0.0f, sum_b = 0.0f;
#pragma unroll
    for (int it = 0; it < 6; it++) {
        float4 v = pA[it * 8];
        sum_a += (v.x + v.y) + (v.z + v.w);
        float4 u = pA[196 + it * 8];
        sum_b += (u.x + u.y) + (u.z + u.w);
    }
    if (j8 == 0) {
        float4 v = pA[48];
        sum_a += (v.x + v.y) + (v.z + v.w);
        float4 u = pA[196 + 48];
        sum_b += (u.x + u.y) + (u.z + u.w);
    }
    // reduce within each 8-lane group
#pragma unroll
    for (int m = 4; m >= 1; m >>= 1) {
        sum_a += __shfl_xor_sync(0xffffffffu, sum_a, m);
        sum_b += __shfl_xor_sync(0xffffffffu, sum_b, m);
    }

    int k = lane & 15;                 // amplitude index owned by this lane
    // per-lane half-angle trig for all 4 wires; fold the row-sign into ss[w]:
    //   ua = ma*c + mp*ss,  up = mp*c - ma*ss
    float cs[4], ss[4];
#pragma unroll
    for (int w = 0; w < 4; w++) {
        float ta = __shfl_sync(0xffffffffu, sum_a, w * 8);
        float tb = __shfl_sync(0xffffffffu, sum_b, w * 8);
        float ang = ((lane < 16) ? ta : tb) * (0.5f / 196.0f);
        float c, s;
        __sincosf(ang, &s, &c);
        if ((k >> (3 - w)) & 1) s = -s;
        cs[w] = c; ss[w] = s;
    }

    // ---- statevector sim: amp(k) per lane ----
    float ar = (k == 0) ? 1.0f : 0.0f;
    float ai = 0.0f;
    const float2* M2 = (const float2*)sM;
#pragma unroll
    for (int l = 0; l < N_LAYERS; l++) {
#pragma unroll
        for (int w = 0; w < 4; w++) {
            int b = (k >> (3 - w)) & 1;
            float2 ma = M2[(l * 4 + w) * 4 + b * 3];      // M[b][b]
            float2 mp = M2[(l * 4 + w) * 4 + b + 1];      // M[b][1-b]
            float c = cs[w], s = ss[w];
            float uar = ma.x * c + mp.x * s;
            float uai = ma.y * c + mp.y * s;
            float upr = mp.x * c - ma.x * s;
            float upi = mp.y * c - ma.y * s;
            float pr = __shfl_xor_sync(0xffffffffu, ar, 8 >> w);
            float pi = __shfl_xor_sync(0xffffffffu, ai, 8 >> w);
            float nr = uar * ar - uai * ai + upr * pr - upi * pi;
            float ni = uar * ai + uai * ar + upr * pi + upi * pr;
            ar = nr; ai = ni;
            if (w < 3) {   // CNOT(w, w+1): permute amps where control bit = 1
                int cm = 8 >> w, tm = 4 >> w;
                int src = (k & cm) ? (lane ^ tm) : lane;
                ar = __shfl_sync(0xffffffffu, ar, src);
                ai = __shfl_sync(0xffffffffu, ai, src);
            }
        }
    }

    // ---- PauliZ expvals ----
    float p = ar * ar + ai * ai;
    float z[4];
#pragma unroll
    for (int w = 0; w < 4; w++) {
        float v = ((k >> (3 - w)) & 1) ? -p : p;
        v += __shfl_xor_sync(0xffffffffu, v, 1);
        v += __shfl_xor_sync(0xffffffffu, v, 2);
        v += __shfl_xor_sync(0xffffffffu, v, 4);
        v += __shfl_xor_sync(0xffffffffu, v, 8);
        z[w] = v;
    }

    // ---- Linear(4,4): lane j (j = k < 4) computes output j of its sample ----
    float o = 0.0f, q = 0.0f;
    if (k < 4) {
        float4 Wr = ((const float4*)Wg)[k];
        o = bg[k] + Wr.x * z[0] + Wr.y * z[1] + Wr.z * z[2] + Wr.w * z[3];
        int s = (lane < 16) ? sA : (sA + 1);
        g_pre[s * 4 + k] = o;
        q = o * o;
    }
    // combine the two samples of this warp, then block-accumulate partials
    float o2 = __shfl_xor_sync(0xffffffffu, o, 16);
    float q2 = __shfl_xor_sync(0xffffffffu, q, 16);
    if (lane < 4) {
        atomicAdd(&sAcc[lane],     o + o2);
        atomicAdd(&sAcc[lane + 4], q + q2);
    }
    __syncthreads();
    if (tid < 8) g_part[blockIdx.x * 8 + tid] = sAcc[tid];   // race-free store
}

// ---------------------------------------------------------------------------
// Kernel 2: reduce per-block partials (L2-resident) + BatchNorm normalize.
// ---------------------------------------------------------------------------
__global__ void __launch_bounds__(256) bn_kernel(const float* __restrict__ bnw,
                                                 const float* __restrict__ bnb,
                                                 float* __restrict__ out) {
    __shared__ float sAcc[8];
    __shared__ float sMu[4], sRs[4];
    int tid = threadIdx.x;
    if (tid < 8) sAcc[tid] = 0.0f;
    __syncthreads();

    // each thread sums rows tid, tid+256, ... of g_part (16 rows of 8 floats)
    float a[8] = {0, 0, 0, 0, 0, 0, 0, 0};
    const float4* p4 = (const float4*)g_part;
#pragma unroll
    for (int it = 0; it < SIM_BLOCKS / 256; it++) {
        int r = it * 256 + tid;
        float4 lo = p4[r * 2 + 0];
        float4 hi = p4[r * 2 + 1];
        a[0] += lo.x; a[1] += lo.y; a[2] += lo.z; a[3] += lo.w;
        a[4] += hi.x; a[5] += hi.y; a[6] += hi.z; a[7] += hi.w;
    }
    // warp reduce, then one shared atomic per warp per slot
#pragma unroll
    for (int j = 0; j < 8; j++) {
#pragma unroll
        for (int m = 16; m >= 1; m >>= 1)
            a[j] += __shfl_xor_sync(0xffffffffu, a[j], m);
    }
    if ((tid & 31) == 0) {
#pragma unroll
        for (int j = 0; j < 8; j++) atomicAdd(&sAcc[j], a[j]);
    }
    __syncthreads();
    if (tid < 4) {
        const float inv = 1.0f / (float)BATCH;
        float mu  = sAcc[tid] * inv;
        float var = sAcc[tid + 4] * inv - mu * mu;
        sMu[tid] = mu;
        sRs[tid] = rsqrtf(var + BN_EPS) * bnw[tid];
    }
    __syncthreads();

    float m0 = sMu[0], m1 = sMu[1], m2 = sMu[2], m3 = sMu[3];
    float r0 = sRs[0], r1 = sRs[1], r2 = sRs[2], r3 = sRs[3];
    float b0 = bnb[0], b1 = bnb[1], b2 = bnb[2], b3 = bnb[3];

    const float4* pre4 = (const float4*)g_pre;
    float4* out4 = (float4*)out;
    int base = blockIdx.x * (BATCH / BN_BLOCKS) + tid;   // 512 samples per block
#pragma unroll
    for (int it = 0; it < (BATCH / BN_BLOCKS) / 256; it++) {
        int i = base + it * 256;
        float4 v = pre4[i];
        float4 r;
        r.x = (v.x - m0) * r0 + b0;
        r.y = (v.y - m1) * r1 + b1;
        r.z = (v.z - m2) * r2 + b2;
        r.w = (v.w - m3) * r3 + b3;
        out4[i] = r;
    }
}

// ---------------------------------------------------------------------------
extern "C" void kernel_launch(void* const* d_in, const int* in_sizes, int n_in,
                              void* d_out, int out_size) {
    const float* x      = (const float*)d_in[0];
    const float* params = (const float*)d_in[1];
    const float* W      = (const float*)d_in[2];
    const float* b      = (const float*)d_in[3];
    const float* bnw    = (const float*)d_in[4];
    const float* bnb    = (const float*)d_in[5];
    float* out = (float*)d_out;

    sim_kernel<<<SIM_BLOCKS, 256>>>(x, params, W, b);   // 16 samples / block
    bn_kernel<<<BN_BLOCKS, 256>>>(bnw, bnb, out);
}

// round 8
// speedup vs baseline: 1.0238x; 1.0238x over previous
#include <cuda_runtime.h>
#include <cuda_bf16.h>

#define BATCH    65536
#define N_WIRES  4
#define N_LAYERS 3
#define BN_EPS   1e-5f
#define SIM_BLOCKS (BATCH / 16)      // 4096 blocks, 16 samples each

// Scratch (no cudaMalloc allowed)
__device__ float g_part[SIM_BLOCKS * 8];   // per-block BN partials: 4 sums + 4 sumsq
__device__ float g_pre[BATCH * 4];         // pre-BN linear outputs
__device__ float g_stats[8];               // BN affine: A[4]=rs, B[4]=bnb-mu*rs
__device__ unsigned int g_ticket;          // zero-init; reset by last block each launch

// ---------------------------------------------------------------------------
// Kernel 1: encode (chunk means) + 4-qubit statevector sim (16 lanes = 16
// amplitudes, 2 samples per warp) + Linear(4,4) + BN partials.
// The LAST block (ticket pattern) reduces all partials into g_stats and
// resets the ticket, so kernel 2 is a pure elementwise stream.
// ---------------------------------------------------------------------------
__global__ void __launch_bounds__(256) sim_kernel(const float* __restrict__ x,
                                                  const float* __restrict__ params,
                                                  const float* __restrict__ Wg,
                                                  const float* __restrict__ bg,
                                                  const float* __restrict__ bnw,
                                                  const float* __restrict__ bnb) {
    __shared__ float sM[96];     // [l][w][row][col][ri]
    __shared__ float sAcc[8];
    __shared__ float sRed[8];
    __shared__ int   sLast;
    int tid = threadIdx.x;
    if (tid < 8) { sAcc[tid] = 0.0f; sRed[tid] = 0.0f; }
    if (tid < 12) {   // tid = l*4 + w : build fused M = RX(t1) @ RZ(t0)
        float t0 = params[tid * 3 + 0];
        float t1 = params[tid * 3 + 1];
        float c0, s0, c1, s1;
        sincosf(0.5f * t0, &s0, &c0);
        sincosf(0.5f * t1, &s1, &c1);
        float2* Mo = (float2*)sM;
        Mo[tid * 4 + 0] = make_float2( c1 * c0, -c1 * s0);
        Mo[tid * 4 + 1] = make_float2( s1 * s0, -s1 * c0);
        Mo[tid * 4 + 2] = make_float2(-s1 * s0, -s1 * c0);
        Mo[tid * 4 + 3] = make_float2( c1 * c0,  c1 * s0);
    }
    __syncthreads();

    int lane = tid & 31;
    int warp = tid >> 5;
    int sA = (blockIdx.x * 8 + warp) * 2;   // warp handles samples sA, sA+1

    // ---- encoding: mean of 4 chunks of 196 floats (49 float4 each) ----
    const float4* x4 = (const float4*)x;
    int g  = lane >> 3;
    int j8 = lane & 7;
    const float4* pA = x4 + (size_t)sA * 196 + g * 49 + j8;
    float sum_a = 0.0f, sum_b = 0.0f;
#pragma unroll
    for (int it = 0; it < 6; it++) {
        float4 v = pA[it * 8];
        sum_a += (v.x + v.y) + (v.z + v.w);
        float4 u = pA[196 + it * 8];
        sum_b += (u.x + u.y) + (u.z + u.w);
    }
    if (j8 == 0) {
        float4 v = pA[48];
        sum_a += (v.x + v.y) + (v.z + v.w);
        float4 u = pA[196 + 48];
        sum_b += (u.x + u.y) + (u.z + u.w);
    }
#pragma unroll
    for (int m = 4; m >= 1; m >>= 1) {
        sum_a += __shfl_xor_sync(0xffffffffu, sum_a, m);
        sum_b += __shfl_xor_sync(0xffffffffu, sum_b, m);
    }

    int k = lane & 15;                 // amplitude index owned by this lane
    float cs[4], ss[4];
#pragma unroll
    for (int w = 0; w < 4; w++) {
        float ta = __shfl_sync(0xffffffffu, sum_a, w * 8);
        float tb = __shfl_sync(0xffffffffu, sum_b, w * 8);
        float ang = ((lane < 16) ? ta : tb) * (0.5f / 196.0f);
        float c, s;
        __sincosf(ang, &s, &c);
        if ((k >> (3 - w)) & 1) s = -s;
        cs[w] = c; ss[w] = s;
    }

    // ---- statevector sim: amp(k) per lane ----
    float ar = (k == 0) ? 1.0f : 0.0f;
    float ai = 0.0f;
    const float2* M2 = (const float2*)sM;
#pragma unroll
    for (int l = 0; l < N_LAYERS; l++) {
#pragma unroll
        for (int w = 0; w < 4; w++) {
            int b = (k >> (3 - w)) & 1;
            float2 ma = M2[(l * 4 + w) * 4 + b * 3];      // M[b][b]
            float2 mp = M2[(l * 4 + w) * 4 + b + 1];      // M[b][1-b]
            float c = cs[w], s = ss[w];
            float uar = ma.x * c + mp.x * s;
            float uai = ma.y * c + mp.y * s;
            float upr = mp.x * c - ma.x * s;
            float upi = mp.y * c - ma.y * s;
            float pr = __shfl_xor_sync(0xffffffffu, ar, 8 >> w);
            float pi = __shfl_xor_sync(0xffffffffu, ai, 8 >> w);
            float nr = uar * ar - uai * ai + upr * pr - upi * pi;
            float ni = uar * ai + uai * ar + upr * pi + upi * pr;
            ar = nr; ai = ni;
            if (w < 3) {   // CNOT(w, w+1)
                int cm = 8 >> w, tm = 4 >> w;
                int src = (k & cm) ? (lane ^ tm) : lane;
                ar = __shfl_sync(0xffffffffu, ar, src);
                ai = __shfl_sync(0xffffffffu, ai, src);
            }
        }
    }

    // ---- PauliZ expvals ----
    float p = ar * ar + ai * ai;
    float z[4];
#pragma unroll
    for (int w = 0; w < 4; w++) {
        float v = ((k >> (3 - w)) & 1) ? -p : p;
        v += __shfl_xor_sync(0xffffffffu, v, 1);
        v += __shfl_xor_sync(0xffffffffu, v, 2);
        v += __shfl_xor_sync(0xffffffffu, v, 4);
        v += __shfl_xor_sync(0xffffffffu, v, 8);
        z[w] = v;
    }

    // ---- Linear(4,4) ----
    float o = 0.0f, q = 0.0f;
    if (k < 4) {
        float4 Wr = ((const float4*)Wg)[k];
        o = bg[k] + Wr.x * z[0] + Wr.y * z[1] + Wr.z * z[2] + Wr.w * z[3];
        int s = (lane < 16) ? sA : (sA + 1);
        g_pre[s * 4 + k] = o;
        q = o * o;
    }
    float o2 = __shfl_xor_sync(0xffffffffu, o, 16);
    float q2 = __shfl_xor_sync(0xffffffffu, q, 16);
    if (lane < 4) {
        atomicAdd(&sAcc[lane],     o + o2);
        atomicAdd(&sAcc[lane + 4], q + q2);
    }
    __syncthreads();
    if (tid < 8) g_part[blockIdx.x * 8 + tid] = sAcc[tid];   // race-free store

    // ---- ticket: last block reduces partials -> g_stats, resets ticket ----
    if (tid == 0) {
        __threadfence();                                // publish g_part row
        unsigned int t = atomicAdd(&g_ticket, 1u);
        sLast = (t == SIM_BLOCKS - 1) ? 1 : 0;
    }
    __syncthreads();
    if (sLast) {
        __threadfence();                                // acquire all g_part rows
        float a[8] = {0, 0, 0, 0, 0, 0, 0, 0};
        const float4* p4 = (const float4*)g_part;
#pragma unroll
        for (int it = 0; it < SIM_BLOCKS / 256; it++) {
            int r = it * 256 + tid;
            float4 lo = p4[r * 2 + 0];
            float4 hi = p4[r * 2 + 1];
            a[0] += lo.x; a[1] += lo.y; a[2] += lo.z; a[3] += lo.w;
            a[4] += hi.x; a[5] += hi.y; a[6] += hi.z; a[7] += hi.w;
        }
#pragma unroll
        for (int j = 0; j < 8; j++) {
#pragma unroll
            for (int m = 16; m >= 1; m >>= 1)
                a[j] += __shfl_xor_sync(0xffffffffu, a[j], m);
        }
        if ((tid & 31) == 0) {
#pragma unroll
            for (int j = 0; j < 8; j++) atomicAdd(&sRed[j], a[j]);
        }
        __syncthreads();
        if (tid < 4) {
            const float inv = 1.0f / (float)BATCH;
            float mu  = sRed[tid] * inv;
            float var = sRed[tid + 4] * inv - mu * mu;
            float rs  = rsqrtf(var + BN_EPS) * bnw[tid];
            g_stats[tid]     = rs;                       // A
            g_stats[tid + 4] = bnb[tid] - mu * rs;       // B
        }
        if (tid == 0) g_ticket = 0;                      // reset for next replay
    }
}

// ---------------------------------------------------------------------------
// Kernel 2: pure elementwise BN apply: out = pre * A + B.
// ---------------------------------------------------------------------------
__global__ void __launch_bounds__(256) bn_kernel(float* __restrict__ out) {
    int i = blockIdx.x * 256 + threadIdx.x;     // one sample (float4) each
    float a0 = g_stats[0], a1 = g_stats[1], a2 = g_stats[2], a3 = g_stats[3];
    float b0 = g_stats[4], b1 = g_stats[5], b2 = g_stats[6], b3 = g_stats[7];
    float4 v = ((const float4*)g_pre)[i];
    float4 r;
    r.x = v.x * a0 + b0;
    r.y = v.y * a1 + b1;
    r.z = v.z * a2 + b2;
    r.w = v.w * a3 + b3;
    ((float4*)out)[i] = r;
}

// ---------------------------------------------------------------------------
extern "C" void kernel_launch(void* const* d_in, const int* in_sizes, int n_in,
                              void* d_out, int out_size) {
    const float* x      = (const float*)d_in[0];
    const float* params = (const float*)d_in[1];
    const float* W      = (const float*)d_in[2];
    const float* b      = (const float*)d_in[3];
    const float* bnw    = (const float*)d_in[4];
    const float* bnb    = (const float*)d_in[5];
    float* out = (float*)d_out;

    sim_kernel<<<SIM_BLOCKS, 256>>>(x, params, W, b, bnw, bnb);
    bn_kernel<<<BATCH / 256, 256>>>(out);
}